// round 16
// baseline (speedup 1.0000x reference)
#include <cuda_runtime.h>
#include <math.h>

#define N 1024
#define D 768
#define H 12
#define DH 64
#define DP 128
#define SCALEF 0.125f

// ---------------- scratch (device globals: no allocation allowed) ----------
__device__ float g_S[(size_t)H * N * N];   // bias -> logits -> probs  (~50 MB)
__device__ float g_x[N * D];               // LN(node)
__device__ float g_qkv[N * 3 * D];         // q|k|v
__device__ float g_g[N * D];               // gate pre-activation
__device__ float g_o[N * D];               // attention output (then gated)
__device__ float g_W2[DP * H];             // ln_w[p]*bias_W[p,h]
__device__ float g_s1[H];                  // sum_p W2[p,h]
__device__ float g_c2[H];                  // sum_p ln_b[p]*bias_W[p,h] + bias_b[h]
__device__ int   g_maskmode;               // 0=float32, 1=int32, 2=uint8

// ---------------- mask dtype probe -----------------------------------------
__global__ void detect_mask_kernel(const void* __restrict__ mask) {
    int t = threadIdx.x;
    bool isf = true, isi = true;
    for (int k = t; k < 2048; k += 256) {
        float v = ((const float*)mask)[k];
        if (!(v == 0.f || v == 1.f)) isf = false;
        int w = ((const int*)mask)[k];
        if (!(w == 0 || w == 1)) isi = false;
    }
    isf = __syncthreads_and(isf);
    isi = __syncthreads_and(isi);
    if (t == 0) g_maskmode = isf ? 0 : (isi ? 1 : 2);
}

// ---------------- fold pair-LN into bias projection -------------------------
__global__ void prep_kernel(const float* __restrict__ biasW, const float* __restrict__ biasb,
                            const float* __restrict__ plw, const float* __restrict__ plb) {
    int t = threadIdx.x;  // 128 threads
    float wl = plw[t];
#pragma unroll
    for (int h = 0; h < H; h++) g_W2[t * H + h] = wl * biasW[t * H + h];
    if (t < H) {
        float s1 = 0.f, c2 = 0.f;
        for (int p = 0; p < DP; p++) {
            float w = biasW[p * H + t];
            s1 += plw[p] * w;
            c2 += plb[p] * w;
        }
        g_s1[t] = s1;
        g_c2[t] = c2 + biasb[t];
    }
}

// ---------------- generic row LayerNorm (len = 768) -------------------------
__global__ void ln_kernel(const float* __restrict__ in, int ldin,
                          float* __restrict__ out, int ldout,
                          const float* __restrict__ w, const float* __restrict__ b) {
    int row = blockIdx.x;
    const float* x = in + (size_t)row * ldin;
    float* o = out + (size_t)row * ldout;
    int t = threadIdx.x;
    float v0 = x[t], v1 = x[t + 256], v2 = x[t + 512];
    float s = v0 + v1 + v2;
    float ss = v0 * v0 + v1 * v1 + v2 * v2;
#pragma unroll
    for (int off = 16; off > 0; off >>= 1) {
        s  += __shfl_xor_sync(0xffffffffu, s, off);
        ss += __shfl_xor_sync(0xffffffffu, ss, off);
    }
    __shared__ float sh[16];
    __shared__ float fm, fr;
    int wid = t >> 5, lane = t & 31;
    if (lane == 0) { sh[wid] = s; sh[8 + wid] = ss; }
    __syncthreads();
    if (t == 0) {
        float S1 = 0.f, S2 = 0.f;
#pragma unroll
        for (int i = 0; i < 8; i++) { S1 += sh[i]; S2 += sh[8 + i]; }
        float m = S1 * (1.f / 768.f);
        float var = S2 * (1.f / 768.f) - m * m;
        fm = m;
        fr = rsqrtf(var + 1e-5f);
    }
    __syncthreads();
    float m = fm, r = fr;
    o[t]       = (v0 - m) * r * w[t]       + b[t];
    o[t + 256] = (v1 - m) * r * w[t + 256] + b[t + 256];
    o[t + 512] = (v2 - m) * r * w[t + 512] + b[t + 512];
}

// ---------------- fp32 GEMM, 64x64 tile (used for small-N GEMMs) ------------
__global__ void gemm_kernel(const float* __restrict__ A, int lda,
                            const float* __restrict__ W, int ldw,
                            const float* __restrict__ bias,
                            float* __restrict__ C, int ldc, int K) {
    __shared__ float As[64][17];
    __shared__ float Ws[16][68];
    int tx = threadIdx.x, ty = threadIdx.y;
    int t = ty * 16 + tx;
    int n0 = blockIdx.x * 64, m0 = blockIdx.y * 64;
    int arow = t >> 2, ak = (t & 3) * 4;
    int wk = t >> 4, wn = (t & 15) * 4;
    const float* Ap = A + (size_t)(m0 + arow) * lda + ak;
    const float* Wp = W + (size_t)wk * ldw + n0 + wn;
    float acc[4][4] = {};
    for (int k0 = 0; k0 < K; k0 += 16) {
        float4 av = *(const float4*)(Ap + k0);
        float4 wv = *(const float4*)(Wp + (size_t)k0 * ldw);
        __syncthreads();
        As[arow][ak + 0] = av.x; As[arow][ak + 1] = av.y;
        As[arow][ak + 2] = av.z; As[arow][ak + 3] = av.w;
        *(float4*)&Ws[wk][wn] = wv;
        __syncthreads();
#pragma unroll
        for (int kk = 0; kk < 16; kk++) {
            float4 b4 = *(const float4*)&Ws[kk][tx * 4];
            float a0 = As[ty * 4 + 0][kk];
            float a1 = As[ty * 4 + 1][kk];
            float a2 = As[ty * 4 + 2][kk];
            float a3 = As[ty * 4 + 3][kk];
            acc[0][0] += a0 * b4.x; acc[0][1] += a0 * b4.y; acc[0][2] += a0 * b4.z; acc[0][3] += a0 * b4.w;
            acc[1][0] += a1 * b4.x; acc[1][1] += a1 * b4.y; acc[1][2] += a1 * b4.z; acc[1][3] += a1 * b4.w;
            acc[2][0] += a2 * b4.x; acc[2][1] += a2 * b4.y; acc[2][2] += a2 * b4.z; acc[2][3] += a2 * b4.w;
            acc[3][0] += a3 * b4.x; acc[3][1] += a3 * b4.y; acc[3][2] += a3 * b4.z; acc[3][3] += a3 * b4.w;
        }
    }
#pragma unroll
    for (int ii = 0; ii < 4; ii++) {
        float* cp = C + (size_t)(m0 + ty * 4 + ii) * ldc + n0 + tx * 4;
#pragma unroll
        for (int jj = 0; jj < 4; jj++) cp[jj] = acc[ii][jj] + bias[n0 + tx * 4 + jj];
    }
}

// ---------------- fp32 GEMM, 128x128 tile, 8x8/thread, double-buffered ------
__global__ void gemm128_kernel(const float* __restrict__ A, int lda,
                               const float* __restrict__ W, int ldw,
                               const float* __restrict__ bias,
                               float* __restrict__ C, int ldc, int K) {
    __shared__ float As[2][8][132];   // [buf][k][m], pad 132 -> conflict-free stores
    __shared__ float Bs[2][8][136];   // [buf][k][n], pad 136 keeps float4 alignment
    int t = threadIdx.x;                       // 256 threads
    int m0 = blockIdx.y * 128, n0 = blockIdx.x * 128;
    int tm = (t >> 4) * 8, tn = (t & 15) * 8;  // per-thread 8x8 tile origin
    int ar = t >> 1, ak = (t & 1) * 4;         // A staging: row ar, k-offset ak
    int bk = t >> 5, bn = (t & 31) * 4;        // B staging: k-row bk, col bn
    const float* Ap = A + (size_t)(m0 + ar) * lda + ak;
    const float* Wp = W + (size_t)bk * ldw + n0 + bn;

    float4 a4 = *(const float4*)Ap;
    float4 b4 = *(const float4*)Wp;
    As[0][ak + 0][ar] = a4.x; As[0][ak + 1][ar] = a4.y;
    As[0][ak + 2][ar] = a4.z; As[0][ak + 3][ar] = a4.w;
    *(float4*)&Bs[0][bk][bn] = b4;
    __syncthreads();

    float acc[8][8] = {};
    int buf = 0;
    for (int k0 = 8; k0 <= K; k0 += 8) {
        if (k0 < K) {
            a4 = *(const float4*)(Ap + k0);
            b4 = *(const float4*)(Wp + (size_t)k0 * ldw);
        }
#pragma unroll
        for (int kk = 0; kk < 8; kk++) {
            float am[8], bv[8];
            *(float4*)&am[0] = *(const float4*)&As[buf][kk][tm];
            *(float4*)&am[4] = *(const float4*)&As[buf][kk][tm + 4];
            *(float4*)&bv[0] = *(const float4*)&Bs[buf][kk][tn];
            *(float4*)&bv[4] = *(const float4*)&Bs[buf][kk][tn + 4];
#pragma unroll
            for (int i = 0; i < 8; i++)
#pragma unroll
                for (int j = 0; j < 8; j++) acc[i][j] += am[i] * bv[j];
        }
        if (k0 < K) {
            buf ^= 1;
            As[buf][ak + 0][ar] = a4.x; As[buf][ak + 1][ar] = a4.y;
            As[buf][ak + 2][ar] = a4.z; As[buf][ak + 3][ar] = a4.w;
            *(float4*)&Bs[buf][bk][bn] = b4;
        }
        __syncthreads();
    }
#pragma unroll
    for (int i = 0; i < 8; i++) {
        float* cp = C + (size_t)(m0 + tm + i) * ldc + n0 + tn;
        float4 o0, o1;
        o0.x = acc[i][0] + bias[n0 + tn + 0];
        o0.y = acc[i][1] + bias[n0 + tn + 1];
        o0.z = acc[i][2] + bias[n0 + tn + 2];
        o0.w = acc[i][3] + bias[n0 + tn + 3];
        o1.x = acc[i][4] + bias[n0 + tn + 4];
        o1.y = acc[i][5] + bias[n0 + tn + 5];
        o1.z = acc[i][6] + bias[n0 + tn + 6];
        o1.w = acc[i][7] + bias[n0 + tn + 7];
        *(float4*)cp = o0;
        *(float4*)(cp + 4) = o1;
    }
}

// ---------------- pair bias v2: one thread per (i,j), register accumulation -
// bias[ij,h] = rstd*(dot(x,W2[:,h]) - m*s1[h]) + c2[h]; stats in registers.
__global__ void pair_bias_kernel(const float* __restrict__ pair, const void* __restrict__ mask) {
    __shared__ float xs[256 * 33];                 // 256 pair rows x 32-col chunk, pad 33
    __shared__ __align__(16) float W2s[DP * H];
    __shared__ float s1s[H], c2s[H];
    int t = threadIdx.x;
    for (int i = t; i < DP * H; i += 256) W2s[i] = g_W2[i];
    if (t < H) { s1s[t] = g_s1[t]; c2s[t] = g_c2[t]; }

    size_t ij0 = (size_t)blockIdx.x * 256;
    const float* pb = pair + ij0 * DP;

    float sum = 0.f, ss = 0.f;
    float y[H];
#pragma unroll
    for (int h = 0; h < H; h++) y[h] = 0.f;

#pragma unroll
    for (int kc = 0; kc < 4; kc++) {
        __syncthreads();   // protects xs reuse (and W2s staging on first pass)
#pragma unroll
        for (int i = 0; i < 8; i++) {
            int f = i * 256 + t;
            int r = f >> 3, c4 = (f & 7) * 4;
            float4 v = *(const float4*)(pb + (size_t)r * DP + kc * 32 + c4);
            float* d = &xs[r * 33 + c4];
            d[0] = v.x; d[1] = v.y; d[2] = v.z; d[3] = v.w;
        }
        __syncthreads();
        const float* xr = &xs[t * 33];
#pragma unroll
        for (int k = 0; k < 32; k++) {
            float xv = xr[k];
            sum += xv; ss += xv * xv;
            const float4* w = (const float4*)&W2s[(kc * 32 + k) * H];
            float4 w0 = w[0], w1 = w[1], w2 = w[2];
            y[0]  += xv * w0.x; y[1]  += xv * w0.y; y[2]  += xv * w0.z; y[3]  += xv * w0.w;
            y[4]  += xv * w1.x; y[5]  += xv * w1.y; y[6]  += xv * w1.z; y[7]  += xv * w1.w;
            y[8]  += xv * w2.x; y[9]  += xv * w2.y; y[10] += xv * w2.z; y[11] += xv * w2.w;
        }
    }

    float m = sum * (1.f / 128.f);
    float var = ss * (1.f / 128.f) - m * m;
    float rstd = rsqrtf(var + 1e-5f);
    size_t ij = ij0 + t;
    int mode = g_maskmode;
    bool mv;
    if (mode == 0)      mv = ((const float*)mask)[ij] != 0.f;
    else if (mode == 1) mv = ((const int*)mask)[ij] != 0;
    else                mv = ((const unsigned char*)mask)[ij] != 0;
    float madd = mv ? 0.f : -10000.f;
#pragma unroll
    for (int h = 0; h < H; h++)
        g_S[((size_t)h << 20) + ij] = rstd * (y[h] - m * s1s[h]) + c2s[h] + madd;
}

// ---------------- logits: S[h] += SCALE * Q_h @ K_h^T -----------------------
__global__ void qk_kernel() {
    __shared__ float Qs[64][65];   // [i][d]
    __shared__ float Ks[64][68];   // [d][j]
    int h = blockIdx.z;
    int i0 = blockIdx.y << 6, j0 = blockIdx.x << 6;
    int tx = threadIdx.x, ty = threadIdx.y;
    int t = ty * 16 + tx;
    int r0 = t >> 4, c4 = (t & 15) * 4;
#pragma unroll
    for (int it = 0; it < 4; it++) {
        int row = it * 16 + r0;
        float4 qv = *(const float4*)&g_qkv[(size_t)(i0 + row) * 2304 + h * 64 + c4];
        Qs[row][c4 + 0] = qv.x; Qs[row][c4 + 1] = qv.y;
        Qs[row][c4 + 2] = qv.z; Qs[row][c4 + 3] = qv.w;
        float4 kv = *(const float4*)&g_qkv[(size_t)(j0 + row) * 2304 + 768 + h * 64 + c4];
        Ks[c4 + 0][row] = kv.x; Ks[c4 + 1][row] = kv.y;
        Ks[c4 + 2][row] = kv.z; Ks[c4 + 3][row] = kv.w;
    }
    __syncthreads();
    float acc[4][4] = {};
#pragma unroll 16
    for (int dd = 0; dd < 64; dd++) {
        float4 b4 = *(const float4*)&Ks[dd][tx * 4];
        float a0 = Qs[ty * 4 + 0][dd];
        float a1 = Qs[ty * 4 + 1][dd];
        float a2 = Qs[ty * 4 + 2][dd];
        float a3 = Qs[ty * 4 + 3][dd];
        acc[0][0] += a0 * b4.x; acc[0][1] += a0 * b4.y; acc[0][2] += a0 * b4.z; acc[0][3] += a0 * b4.w;
        acc[1][0] += a1 * b4.x; acc[1][1] += a1 * b4.y; acc[1][2] += a1 * b4.z; acc[1][3] += a1 * b4.w;
        acc[2][0] += a2 * b4.x; acc[2][1] += a2 * b4.y; acc[2][2] += a2 * b4.z; acc[2][3] += a2 * b4.w;
        acc[3][0] += a3 * b4.x; acc[3][1] += a3 * b4.y; acc[3][2] += a3 * b4.z; acc[3][3] += a3 * b4.w;
    }
#pragma unroll
    for (int ii = 0; ii < 4; ii++) {
        float4* sp = (float4*)&g_S[((size_t)h << 20) + ((size_t)(i0 + ty * 4 + ii) << 10) + j0 + tx * 4];
        float4 sv = *sp;
        sv.x += SCALEF * acc[ii][0];
        sv.y += SCALEF * acc[ii][1];
        sv.z += SCALEF * acc[ii][2];
        sv.w += SCALEF * acc[ii][3];
        *sp = sv;
    }
}

// ---------------- row softmax over S (row len 1024) --------------------------
__global__ void softmax_kernel() {
    float* p = g_S + ((size_t)blockIdx.x << 10);
    int t = threadIdx.x;
    float4 v = ((float4*)p)[t];
    float m = fmaxf(fmaxf(v.x, v.y), fmaxf(v.z, v.w));
#pragma unroll
    for (int off = 16; off > 0; off >>= 1) m = fmaxf(m, __shfl_xor_sync(0xffffffffu, m, off));
    __shared__ float sh[8];
    __shared__ float gm, gz;
    int wid = t >> 5, lane = t & 31;
    if (lane == 0) sh[wid] = m;
    __syncthreads();
    if (t == 0) {
        float mm = sh[0];
#pragma unroll
        for (int i = 1; i < 8; i++) mm = fmaxf(mm, sh[i]);
        gm = mm;
    }
    __syncthreads();
    float M = gm;
    float e0 = __expf(v.x - M), e1 = __expf(v.y - M), e2 = __expf(v.z - M), e3 = __expf(v.w - M);
    float s = e0 + e1 + e2 + e3;
#pragma unroll
    for (int off = 16; off > 0; off >>= 1) s += __shfl_xor_sync(0xffffffffu, s, off);
    if (lane == 0) sh[wid] = s;
    __syncthreads();
    if (t == 0) {
        float z = 0.f;
#pragma unroll
        for (int i = 0; i < 8; i++) z += sh[i];
        gz = z;
    }
    __syncthreads();
    float inv = 1.f / gz;
    v.x = e0 * inv; v.y = e1 * inv; v.z = e2 * inv; v.w = e3 * inv;
    ((float4*)p)[t] = v;
}

// ---------------- O = P_h @ V_h  (32x64 tile per block) ----------------------
__global__ void pv_kernel() {
    __shared__ float As[32][17];
    __shared__ float Ws[16][68];
    int h = blockIdx.y;
    int i0 = blockIdx.x << 5;
    int tx = threadIdx.x, ty = threadIdx.y;  // (16,8)
    int t = ty * 16 + tx;
    int arow = t >> 2, ak = (t & 3) * 4;
    int wn = (t & 15) * 4, wk0 = t >> 4;     // wk0 in 0..7
    const float* Sp = g_S + ((size_t)h << 20) + ((size_t)(i0 + arow) << 10) + ak;
    const float* Vp = g_qkv + 1536 + h * 64 + wn;
    float acc[4][4] = {};
    for (int k0 = 0; k0 < 1024; k0 += 16) {
        float4 av  = *(const float4*)(Sp + k0);
        float4 wv0 = *(const float4*)(Vp + (size_t)(k0 + wk0) * 2304);
        float4 wv1 = *(const float4*)(Vp + (size_t)(k0 + wk0 + 8) * 2304);
        __syncthreads();
        As[arow][ak + 0] = av.x; As[arow][ak + 1] = av.y;
        As[arow][ak + 2] = av.z; As[arow][ak + 3] = av.w;
        *(float4*)&Ws[wk0][wn]     = wv0;
        *(float4*)&Ws[wk0 + 8][wn] = wv1;
        __syncthreads();
#pragma unroll
        for (int kk = 0; kk < 16; kk++) {
            float4 b4 = *(const float4*)&Ws[kk][tx * 4];
            float a0 = As[ty * 4 + 0][kk];
            float a1 = As[ty * 4 + 1][kk];
            float a2 = As[ty * 4 + 2][kk];
            float a3 = As[ty * 4 + 3][kk];
            acc[0][0] += a0 * b4.x; acc[0][1] += a0 * b4.y; acc[0][2] += a0 * b4.z; acc[0][3] += a0 * b4.w;
            acc[1][0] += a1 * b4.x; acc[1][1] += a1 * b4.y; acc[1][2] += a1 * b4.z; acc[1][3] += a1 * b4.w;
            acc[2][0] += a2 * b4.x; acc[2][1] += a2 * b4.y; acc[2][2] += a2 * b4.z; acc[2][3] += a2 * b4.w;
            acc[3][0] += a3 * b4.x; acc[3][1] += a3 * b4.y; acc[3][2] += a3 * b4.z; acc[3][3] += a3 * b4.w;
        }
    }
#pragma unroll
    for (int ii = 0; ii < 4; ii++) {
        float* op = g_o + (size_t)(i0 + ty * 4 + ii) * 768 + h * 64 + tx * 4;
#pragma unroll
        for (int jj = 0; jj < 4; jj++) op[jj] = acc[ii][jj];
    }
}

// ---------------- gate: o *= sigmoid(g) --------------------------------------
__global__ void gate_kernel() {
    int idx = blockIdx.x * 256 + threadIdx.x;
    float4 ov = ((float4*)g_o)[idx];
    float4 gv = ((float4*)g_g)[idx];
    ov.x *= 1.f / (1.f + __expf(-gv.x));
    ov.y *= 1.f / (1.f + __expf(-gv.y));
    ov.z *= 1.f / (1.f + __expf(-gv.z));
    ov.w *= 1.f / (1.f + __expf(-gv.w));
    ((float4*)g_o)[idx] = ov;
}

// ---------------- launch ------------------------------------------------------
extern "C" void kernel_launch(void* const* d_in, const int* in_sizes, int n_in,
                              void* d_out, int out_size) {
    const float* node  = (const float*)d_in[0];
    const float* pair  = (const float*)d_in[1];
    const float* lnw   = (const float*)d_in[2];
    const float* lnb   = (const float*)d_in[3];
    const float* plw   = (const float*)d_in[4];
    const float* plb   = (const float*)d_in[5];
    const float* qkvW  = (const float*)d_in[6];
    const float* qkvb  = (const float*)d_in[7];
    const float* qlw   = (const float*)d_in[8];
    const float* qlb   = (const float*)d_in[9];
    const float* klw   = (const float*)d_in[10];
    const float* klb   = (const float*)d_in[11];
    const float* gW    = (const float*)d_in[12];
    const float* gb    = (const float*)d_in[13];
    const float* biasW = (const float*)d_in[14];
    const float* biasb = (const float*)d_in[15];
    const float* outW  = (const float*)d_in[16];
    const float* outb  = (const float*)d_in[17];
    const void*  mask  = d_in[18];
    float* out = (float*)d_out;

    float *xp, *qkvp, *gp, *op;
    cudaGetSymbolAddress((void**)&xp,   g_x);
    cudaGetSymbolAddress((void**)&qkvp, g_qkv);
    cudaGetSymbolAddress((void**)&gp,   g_g);
    cudaGetSymbolAddress((void**)&op,   g_o);

    detect_mask_kernel<<<1, 256>>>(mask);
    prep_kernel<<<1, 128>>>(biasW, biasb, plw, plb);

    // node path
    ln_kernel<<<N, 256>>>(node, D, xp, D, lnw, lnb);
    gemm128_kernel<<<dim3(2304 / 128, 1024 / 128), 256>>>(xp, D, qkvW, 2304, qkvb, qkvp, 2304, D);
    gemm_kernel<<<dim3(12, 16), dim3(16, 16)>>>(xp, D, gW, D, gb, gp, D, D);
    ln_kernel<<<N, 256>>>(qkvp, 2304, qkvp, 2304, qlw, qlb);
    ln_kernel<<<N, 256>>>(qkvp + 768, 2304, qkvp + 768, 2304, klw, klb);

    // pair path: bias + mask into S  (256 pairs per block)
    pair_bias_kernel<<<N * N / 256, 256>>>(pair, mask);

    // attention
    qk_kernel<<<dim3(16, 16, 12), dim3(16, 16)>>>();
    softmax_kernel<<<H * N, 256>>>();
    pv_kernel<<<dim3(32, 12), dim3(16, 8)>>>();

    // gate + output projection
    gate_kernel<<<N * D / 1024, 256>>>();
    gemm_kernel<<<dim3(12, 16), dim3(16, 16)>>>(op, D, outW, D, outb, out, D, D);
}

// round 17
// speedup vs baseline: 1.0043x; 1.0043x over previous
#include <cuda_runtime.h>
#include <math.h>

#define N 1024
#define D 768
#define H 12
#define DH 64
#define DP 128
#define SCALEF 0.125f

// ---------------- scratch (device globals: no allocation allowed) ----------
__device__ float g_S[(size_t)H * N * N];   // bias -> logits -> probs  (~50 MB)
__device__ float g_x[N * D];               // LN(node)
__device__ float g_qkv[N * 3 * D];         // q|k|v
__device__ float g_g[N * D];               // gate pre-activation
__device__ float g_o[N * D];               // attention output (then gated)
__device__ float g_W2[DP * H];             // ln_w[p]*bias_W[p,h]
__device__ float g_s1[H];                  // sum_p W2[p,h]
__device__ float g_c2[H];                  // sum_p ln_b[p]*bias_W[p,h] + bias_b[h]
__device__ int   g_maskmode;               // 0=float32, 1=int32, 2=uint8

// ---------------- mask dtype probe -----------------------------------------
__global__ void detect_mask_kernel(const void* __restrict__ mask) {
    int t = threadIdx.x;
    bool isf = true, isi = true;
    for (int k = t; k < 2048; k += 256) {
        float v = ((const float*)mask)[k];
        if (!(v == 0.f || v == 1.f)) isf = false;
        int w = ((const int*)mask)[k];
        if (!(w == 0 || w == 1)) isi = false;
    }
    isf = __syncthreads_and(isf);
    isi = __syncthreads_and(isi);
    if (t == 0) g_maskmode = isf ? 0 : (isi ? 1 : 2);
}

// ---------------- fold pair-LN into bias projection -------------------------
__global__ void prep_kernel(const float* __restrict__ biasW, const float* __restrict__ biasb,
                            const float* __restrict__ plw, const float* __restrict__ plb) {
    int t = threadIdx.x;  // 128 threads
    float wl = plw[t];
#pragma unroll
    for (int h = 0; h < H; h++) g_W2[t * H + h] = wl * biasW[t * H + h];
    if (t < H) {
        float s1 = 0.f, c2 = 0.f;
        for (int p = 0; p < DP; p++) {
            float w = biasW[p * H + t];
            s1 += plw[p] * w;
            c2 += plb[p] * w;
        }
        g_s1[t] = s1;
        g_c2[t] = c2 + biasb[t];
    }
}

// ---------------- generic row LayerNorm (len = 768) -------------------------
__global__ void ln_kernel(const float* __restrict__ in, int ldin,
                          float* __restrict__ out, int ldout,
                          const float* __restrict__ w, const float* __restrict__ b) {
    int row = blockIdx.x;
    const float* x = in + (size_t)row * ldin;
    float* o = out + (size_t)row * ldout;
    int t = threadIdx.x;
    float v0 = x[t], v1 = x[t + 256], v2 = x[t + 512];
    float s = v0 + v1 + v2;
    float ss = v0 * v0 + v1 * v1 + v2 * v2;
#pragma unroll
    for (int off = 16; off > 0; off >>= 1) {
        s  += __shfl_xor_sync(0xffffffffu, s, off);
        ss += __shfl_xor_sync(0xffffffffu, ss, off);
    }
    __shared__ float sh[16];
    __shared__ float fm, fr;
    int wid = t >> 5, lane = t & 31;
    if (lane == 0) { sh[wid] = s; sh[8 + wid] = ss; }
    __syncthreads();
    if (t == 0) {
        float S1 = 0.f, S2 = 0.f;
#pragma unroll
        for (int i = 0; i < 8; i++) { S1 += sh[i]; S2 += sh[8 + i]; }
        float m = S1 * (1.f / 768.f);
        float var = S2 * (1.f / 768.f) - m * m;
        fm = m;
        fr = rsqrtf(var + 1e-5f);
    }
    __syncthreads();
    float m = fm, r = fr;
    o[t]       = (v0 - m) * r * w[t]       + b[t];
    o[t + 256] = (v1 - m) * r * w[t + 256] + b[t + 256];
    o[t + 512] = (v2 - m) * r * w[t + 512] + b[t + 512];
}

// ---------------- fp32 GEMM, 64x64 tile (used for small-N GEMMs) ------------
__global__ void gemm_kernel(const float* __restrict__ A, int lda,
                            const float* __restrict__ W, int ldw,
                            const float* __restrict__ bias,
                            float* __restrict__ C, int ldc, int K) {
    __shared__ float As[64][17];
    __shared__ float Ws[16][68];
    int tx = threadIdx.x, ty = threadIdx.y;
    int t = ty * 16 + tx;
    int n0 = blockIdx.x * 64, m0 = blockIdx.y * 64;
    int arow = t >> 2, ak = (t & 3) * 4;
    int wk = t >> 4, wn = (t & 15) * 4;
    const float* Ap = A + (size_t)(m0 + arow) * lda + ak;
    const float* Wp = W + (size_t)wk * ldw + n0 + wn;
    float acc[4][4] = {};
    for (int k0 = 0; k0 < K; k0 += 16) {
        float4 av = *(const float4*)(Ap + k0);
        float4 wv = *(const float4*)(Wp + (size_t)k0 * ldw);
        __syncthreads();
        As[arow][ak + 0] = av.x; As[arow][ak + 1] = av.y;
        As[arow][ak + 2] = av.z; As[arow][ak + 3] = av.w;
        *(float4*)&Ws[wk][wn] = wv;
        __syncthreads();
#pragma unroll
        for (int kk = 0; kk < 16; kk++) {
            float4 b4 = *(const float4*)&Ws[kk][tx * 4];
            float a0 = As[ty * 4 + 0][kk];
            float a1 = As[ty * 4 + 1][kk];
            float a2 = As[ty * 4 + 2][kk];
            float a3 = As[ty * 4 + 3][kk];
            acc[0][0] += a0 * b4.x; acc[0][1] += a0 * b4.y; acc[0][2] += a0 * b4.z; acc[0][3] += a0 * b4.w;
            acc[1][0] += a1 * b4.x; acc[1][1] += a1 * b4.y; acc[1][2] += a1 * b4.z; acc[1][3] += a1 * b4.w;
            acc[2][0] += a2 * b4.x; acc[2][1] += a2 * b4.y; acc[2][2] += a2 * b4.z; acc[2][3] += a2 * b4.w;
            acc[3][0] += a3 * b4.x; acc[3][1] += a3 * b4.y; acc[3][2] += a3 * b4.z; acc[3][3] += a3 * b4.w;
        }
    }
#pragma unroll
    for (int ii = 0; ii < 4; ii++) {
        float* cp = C + (size_t)(m0 + ty * 4 + ii) * ldc + n0 + tx * 4;
#pragma unroll
        for (int jj = 0; jj < 4; jj++) cp[jj] = acc[ii][jj] + bias[n0 + tx * 4 + jj];
    }
}

// ---------------- fp32 GEMM, 128x128 tile, 8x8/thread, double-buffered ------
__global__ void gemm128_kernel(const float* __restrict__ A, int lda,
                               const float* __restrict__ W, int ldw,
                               const float* __restrict__ bias,
                               float* __restrict__ C, int ldc, int K) {
    __shared__ float As[2][8][132];   // [buf][k][m], pad 132 -> conflict-free stores
    __shared__ float Bs[2][8][136];   // [buf][k][n], pad 136 keeps float4 alignment
    int t = threadIdx.x;                       // 256 threads
    int m0 = blockIdx.y * 128, n0 = blockIdx.x * 128;
    int tm = (t >> 4) * 8, tn = (t & 15) * 8;  // per-thread 8x8 tile origin
    int ar = t >> 1, ak = (t & 1) * 4;         // A staging: row ar, k-offset ak
    int bk = t >> 5, bn = (t & 31) * 4;        // B staging: k-row bk, col bn
    const float* Ap = A + (size_t)(m0 + ar) * lda + ak;
    const float* Wp = W + (size_t)bk * ldw + n0 + bn;

    float4 a4 = *(const float4*)Ap;
    float4 b4 = *(const float4*)Wp;
    As[0][ak + 0][ar] = a4.x; As[0][ak + 1][ar] = a4.y;
    As[0][ak + 2][ar] = a4.z; As[0][ak + 3][ar] = a4.w;
    *(float4*)&Bs[0][bk][bn] = b4;
    __syncthreads();

    float acc[8][8] = {};
    int buf = 0;
    for (int k0 = 8; k0 <= K; k0 += 8) {
        if (k0 < K) {
            a4 = *(const float4*)(Ap + k0);
            b4 = *(const float4*)(Wp + (size_t)k0 * ldw);
        }
#pragma unroll
        for (int kk = 0; kk < 8; kk++) {
            float am[8], bv[8];
            *(float4*)&am[0] = *(const float4*)&As[buf][kk][tm];
            *(float4*)&am[4] = *(const float4*)&As[buf][kk][tm + 4];
            *(float4*)&bv[0] = *(const float4*)&Bs[buf][kk][tn];
            *(float4*)&bv[4] = *(const float4*)&Bs[buf][kk][tn + 4];
#pragma unroll
            for (int i = 0; i < 8; i++)
#pragma unroll
                for (int j = 0; j < 8; j++) acc[i][j] += am[i] * bv[j];
        }
        if (k0 < K) {
            buf ^= 1;
            As[buf][ak + 0][ar] = a4.x; As[buf][ak + 1][ar] = a4.y;
            As[buf][ak + 2][ar] = a4.z; As[buf][ak + 3][ar] = a4.w;
            *(float4*)&Bs[buf][bk][bn] = b4;
        }
        __syncthreads();
    }
#pragma unroll
    for (int i = 0; i < 8; i++) {
        float* cp = C + (size_t)(m0 + tm + i) * ldc + n0 + tn;
        float4 o0, o1;
        o0.x = acc[i][0] + bias[n0 + tn + 0];
        o0.y = acc[i][1] + bias[n0 + tn + 1];
        o0.z = acc[i][2] + bias[n0 + tn + 2];
        o0.w = acc[i][3] + bias[n0 + tn + 3];
        o1.x = acc[i][4] + bias[n0 + tn + 4];
        o1.y = acc[i][5] + bias[n0 + tn + 5];
        o1.z = acc[i][6] + bias[n0 + tn + 6];
        o1.w = acc[i][7] + bias[n0 + tn + 7];
        *(float4*)cp = o0;
        *(float4*)(cp + 4) = o1;
    }
}

// ---------------- pair bias v2: one thread per (i,j), register accumulation -
// bias[ij,h] = rstd*(dot(x,W2[:,h]) - m*s1[h]) + c2[h]; stats in registers.
__global__ void pair_bias_kernel(const float* __restrict__ pair, const void* __restrict__ mask) {
    __shared__ float xs[256 * 33];                 // 256 pair rows x 32-col chunk, pad 33
    __shared__ __align__(16) float W2s[DP * H];
    __shared__ float s1s[H], c2s[H];
    int t = threadIdx.x;
    for (int i = t; i < DP * H; i += 256) W2s[i] = g_W2[i];
    if (t < H) { s1s[t] = g_s1[t]; c2s[t] = g_c2[t]; }

    size_t ij0 = (size_t)blockIdx.x * 256;
    const float* pb = pair + ij0 * DP;

    float sum = 0.f, ss = 0.f;
    float y[H];
#pragma unroll
    for (int h = 0; h < H; h++) y[h] = 0.f;

#pragma unroll
    for (int kc = 0; kc < 4; kc++) {
        __syncthreads();   // protects xs reuse (and W2s staging on first pass)
#pragma unroll
        for (int i = 0; i < 8; i++) {
            int f = i * 256 + t;
            int r = f >> 3, c4 = (f & 7) * 4;
            float4 v = *(const float4*)(pb + (size_t)r * DP + kc * 32 + c4);
            float* d = &xs[r * 33 + c4];
            d[0] = v.x; d[1] = v.y; d[2] = v.z; d[3] = v.w;
        }
        __syncthreads();
        const float* xr = &xs[t * 33];
#pragma unroll
        for (int k = 0; k < 32; k++) {
            float xv = xr[k];
            sum += xv; ss += xv * xv;
            const float4* w = (const float4*)&W2s[(kc * 32 + k) * H];
            float4 w0 = w[0], w1 = w[1], w2 = w[2];
            y[0]  += xv * w0.x; y[1]  += xv * w0.y; y[2]  += xv * w0.z; y[3]  += xv * w0.w;
            y[4]  += xv * w1.x; y[5]  += xv * w1.y; y[6]  += xv * w1.z; y[7]  += xv * w1.w;
            y[8]  += xv * w2.x; y[9]  += xv * w2.y; y[10] += xv * w2.z; y[11] += xv * w2.w;
        }
    }

    float m = sum * (1.f / 128.f);
    float var = ss * (1.f / 128.f) - m * m;
    float rstd = rsqrtf(var + 1e-5f);
    size_t ij = ij0 + t;
    int mode = g_maskmode;
    bool mv;
    if (mode == 0)      mv = ((const float*)mask)[ij] != 0.f;
    else if (mode == 1) mv = ((const int*)mask)[ij] != 0;
    else                mv = ((const unsigned char*)mask)[ij] != 0;
    float madd = mv ? 0.f : -10000.f;
#pragma unroll
    for (int h = 0; h < H; h++)
        g_S[((size_t)h << 20) + ij] = rstd * (y[h] - m * s1s[h]) + c2s[h] + madd;
}

// ---------------- logits: S[h] += SCALE * Q_h @ K_h^T -----------------------
__global__ void qk_kernel() {
    __shared__ float Qs[64][65];   // [i][d]
    __shared__ float Ks[64][68];   // [d][j]
    int h = blockIdx.z;
    int i0 = blockIdx.y << 6, j0 = blockIdx.x << 6;
    int tx = threadIdx.x, ty = threadIdx.y;
    int t = ty * 16 + tx;
    int r0 = t >> 4, c4 = (t & 15) * 4;
#pragma unroll
    for (int it = 0; it < 4; it++) {
        int row = it * 16 + r0;
        float4 qv = *(const float4*)&g_qkv[(size_t)(i0 + row) * 2304 + h * 64 + c4];
        Qs[row][c4 + 0] = qv.x; Qs[row][c4 + 1] = qv.y;
        Qs[row][c4 + 2] = qv.z; Qs[row][c4 + 3] = qv.w;
        float4 kv = *(const float4*)&g_qkv[(size_t)(j0 + row) * 2304 + 768 + h * 64 + c4];
        Ks[c4 + 0][row] = kv.x; Ks[c4 + 1][row] = kv.y;
        Ks[c4 + 2][row] = kv.z; Ks[c4 + 3][row] = kv.w;
    }
    __syncthreads();
    float acc[4][4] = {};
#pragma unroll 16
    for (int dd = 0; dd < 64; dd++) {
        float4 b4 = *(const float4*)&Ks[dd][tx * 4];
        float a0 = Qs[ty * 4 + 0][dd];
        float a1 = Qs[ty * 4 + 1][dd];
        float a2 = Qs[ty * 4 + 2][dd];
        float a3 = Qs[ty * 4 + 3][dd];
        acc[0][0] += a0 * b4.x; acc[0][1] += a0 * b4.y; acc[0][2] += a0 * b4.z; acc[0][3] += a0 * b4.w;
        acc[1][0] += a1 * b4.x; acc[1][1] += a1 * b4.y; acc[1][2] += a1 * b4.z; acc[1][3] += a1 * b4.w;
        acc[2][0] += a2 * b4.x; acc[2][1] += a2 * b4.y; acc[2][2] += a2 * b4.z; acc[2][3] += a2 * b4.w;
        acc[3][0] += a3 * b4.x; acc[3][1] += a3 * b4.y; acc[3][2] += a3 * b4.z; acc[3][3] += a3 * b4.w;
    }
#pragma unroll
    for (int ii = 0; ii < 4; ii++) {
        float4* sp = (float4*)&g_S[((size_t)h << 20) + ((size_t)(i0 + ty * 4 + ii) << 10) + j0 + tx * 4];
        float4 sv = *sp;
        sv.x += SCALEF * acc[ii][0];
        sv.y += SCALEF * acc[ii][1];
        sv.z += SCALEF * acc[ii][2];
        sv.w += SCALEF * acc[ii][3];
        *sp = sv;
    }
}

// ---------------- row softmax over S (row len 1024) --------------------------
__global__ void softmax_kernel() {
    float* p = g_S + ((size_t)blockIdx.x << 10);
    int t = threadIdx.x;
    float4 v = ((float4*)p)[t];
    float m = fmaxf(fmaxf(v.x, v.y), fmaxf(v.z, v.w));
#pragma unroll
    for (int off = 16; off > 0; off >>= 1) m = fmaxf(m, __shfl_xor_sync(0xffffffffu, m, off));
    __shared__ float sh[8];
    __shared__ float gm, gz;
    int wid = t >> 5, lane = t & 31;
    if (lane == 0) sh[wid] = m;
    __syncthreads();
    if (t == 0) {
        float mm = sh[0];
#pragma unroll
        for (int i = 1; i < 8; i++) mm = fmaxf(mm, sh[i]);
        gm = mm;
    }
    __syncthreads();
    float M = gm;
    float e0 = __expf(v.x - M), e1 = __expf(v.y - M), e2 = __expf(v.z - M), e3 = __expf(v.w - M);
    float s = e0 + e1 + e2 + e3;
#pragma unroll
    for (int off = 16; off > 0; off >>= 1) s += __shfl_xor_sync(0xffffffffu, s, off);
    if (lane == 0) sh[wid] = s;
    __syncthreads();
    if (t == 0) {
        float z = 0.f;
#pragma unroll
        for (int i = 0; i < 8; i++) z += sh[i];
        gz = z;
    }
    __syncthreads();
    float inv = 1.f / gz;
    v.x = e0 * inv; v.y = e1 * inv; v.z = e2 * inv; v.w = e3 * inv;
    ((float4*)p)[t] = v;
}

// ---------------- O = P_h @ V_h  (32x64 tile per block) ----------------------
__global__ void pv_kernel() {
    __shared__ float As[32][17];
    __shared__ float Ws[16][68];
    int h = blockIdx.y;
    int i0 = blockIdx.x << 5;
    int tx = threadIdx.x, ty = threadIdx.y;  // (16,8)
    int t = ty * 16 + tx;
    int arow = t >> 2, ak = (t & 3) * 4;
    int wn = (t & 15) * 4, wk0 = t >> 4;     // wk0 in 0..7
    const float* Sp = g_S + ((size_t)h << 20) + ((size_t)(i0 + arow) << 10) + ak;
    const float* Vp = g_qkv + 1536 + h * 64 + wn;
    float acc[4][4] = {};
    for (int k0 = 0; k0 < 1024; k0 += 16) {
        float4 av  = *(const float4*)(Sp + k0);
        float4 wv0 = *(const float4*)(Vp + (size_t)(k0 + wk0) * 2304);
        float4 wv1 = *(const float4*)(Vp + (size_t)(k0 + wk0 + 8) * 2304);
        __syncthreads();
        As[arow][ak + 0] = av.x; As[arow][ak + 1] = av.y;
        As[arow][ak + 2] = av.z; As[arow][ak + 3] = av.w;
        *(float4*)&Ws[wk0][wn]     = wv0;
        *(float4*)&Ws[wk0 + 8][wn] = wv1;
        __syncthreads();
#pragma unroll
        for (int kk = 0; kk < 16; kk++) {
            float4 b4 = *(const float4*)&Ws[kk][tx * 4];
            float a0 = As[ty * 4 + 0][kk];
            float a1 = As[ty * 4 + 1][kk];
            float a2 = As[ty * 4 + 2][kk];
            float a3 = As[ty * 4 + 3][kk];
            acc[0][0] += a0 * b4.x; acc[0][1] += a0 * b4.y; acc[0][2] += a0 * b4.z; acc[0][3] += a0 * b4.w;
            acc[1][0] += a1 * b4.x; acc[1][1] += a1 * b4.y; acc[1][2] += a1 * b4.z; acc[1][3] += a1 * b4.w;
            acc[2][0] += a2 * b4.x; acc[2][1] += a2 * b4.y; acc[2][2] += a2 * b4.z; acc[2][3] += a2 * b4.w;
            acc[3][0] += a3 * b4.x; acc[3][1] += a3 * b4.y; acc[3][2] += a3 * b4.z; acc[3][3] += a3 * b4.w;
        }
    }
#pragma unroll
    for (int ii = 0; ii < 4; ii++) {
        float* op = g_o + (size_t)(i0 + ty * 4 + ii) * 768 + h * 64 + tx * 4;
#pragma unroll
        for (int jj = 0; jj < 4; jj++) op[jj] = acc[ii][jj];
    }
}

// ---------------- gate: o *= sigmoid(g) --------------------------------------
__global__ void gate_kernel() {
    int idx = blockIdx.x * 256 + threadIdx.x;
    float4 ov = ((float4*)g_o)[idx];
    float4 gv = ((float4*)g_g)[idx];
    ov.x *= 1.f / (1.f + __expf(-gv.x));
    ov.y *= 1.f / (1.f + __expf(-gv.y));
    ov.z *= 1.f / (1.f + __expf(-gv.z));
    ov.w *= 1.f / (1.f + __expf(-gv.w));
    ((float4*)g_o)[idx] = ov;
}

// ---------------- launch ------------------------------------------------------
extern "C" void kernel_launch(void* const* d_in, const int* in_sizes, int n_in,
                              void* d_out, int out_size) {
    const float* node  = (const float*)d_in[0];
    const float* pair  = (const float*)d_in[1];
    const float* lnw   = (const float*)d_in[2];
    const float* lnb   = (const float*)d_in[3];
    const float* plw   = (const float*)d_in[4];
    const float* plb   = (const float*)d_in[5];
    const float* qkvW  = (const float*)d_in[6];
    const float* qkvb  = (const float*)d_in[7];
    const float* qlw   = (const float*)d_in[8];
    const float* qlb   = (const float*)d_in[9];
    const float* klw   = (const float*)d_in[10];
    const float* klb   = (const float*)d_in[11];
    const float* gW    = (const float*)d_in[12];
    const float* gb    = (const float*)d_in[13];
    const float* biasW = (const float*)d_in[14];
    const float* biasb = (const float*)d_in[15];
    const float* outW  = (const float*)d_in[16];
    const float* outb  = (const float*)d_in[17];
    const void*  mask  = d_in[18];
    float* out = (float*)d_out;

    float *xp, *qkvp, *gp, *op;
    cudaGetSymbolAddress((void**)&xp,   g_x);
    cudaGetSymbolAddress((void**)&qkvp, g_qkv);
    cudaGetSymbolAddress((void**)&gp,   g_g);
    cudaGetSymbolAddress((void**)&op,   g_o);

    detect_mask_kernel<<<1, 256>>>(mask);
    prep_kernel<<<1, 128>>>(biasW, biasb, plw, plb);

    // node path
    ln_kernel<<<N, 256>>>(node, D, xp, D, lnw, lnb);
    gemm128_kernel<<<dim3(2304 / 128, 1024 / 128), 256>>>(xp, D, qkvW, 2304, qkvb, qkvp, 2304, D);
    gemm_kernel<<<dim3(12, 16), dim3(16, 16)>>>(xp, D, gW, D, gb, gp, D, D);
    ln_kernel<<<N, 256>>>(qkvp, 2304, qkvp, 2304, qlw, qlb);
    ln_kernel<<<N, 256>>>(qkvp + 768, 2304, qkvp + 768, 2304, klw, klb);

    // pair path: bias + mask into S  (256 pairs per block)
    pair_bias_kernel<<<N * N / 256, 256>>>(pair, mask);

    // attention
    qk_kernel<<<dim3(16, 16, 12), dim3(16, 16)>>>();
    softmax_kernel<<<H * N, 256>>>();
    pv_kernel<<<dim3(32, 12), dim3(16, 8)>>>();

    // gate + output projection
    gate_kernel<<<N * D / 1024, 256>>>();
    gemm_kernel<<<dim3(12, 16), dim3(16, 16)>>>(op, D, outW, D, outb, out, D, D);
}